// round 15
// baseline (speedup 1.0000x reference)
#include <cuda_runtime.h>
#include <cuda_fp16.h>
#include <cstdint>

// ============================================================================
// y = x @ W^T + b (4096^3 fp32), mma.sync.m16n8k16.f32.f16.f16.f32.
//
// Round-15 = round-14 GEMM core (CTA 128x128, 4 warps of 64x64, BK=64,
// 3-stage cp.async, 2 CTA/SM, SW-pipelined steps, B frags packing both
// ks-steps) restructured as 296 PERSISTENT CTAs (one wave, 2/SM) popping
// 1160 tasks (888 full-K tiles + 272 half-K halves) from a global atomic
// counter. Kills multi-CTA spread (fast SMs take more tasks) and wave
// transitions. Split-K reduction: symmetric second-finisher via atomicExch
// (no spinning; commutative fp32 add -> bitwise deterministic).
// ============================================================================

#define KDIM 4096
#define STAGES 3
#define A_STG 16384                       // 128 x 64 x 2B
#define B_STG 16384
#define STG (A_STG + B_STG)               // 32768
#define SMEM_TOTAL (STAGES * STG)         // 98304

#define FULL_TILES 888                    // 3 x 296
#define SPLIT_TILES 136
#define NTASKS (FULL_TILES + 2 * SPLIT_TILES)   // 1160
#define GRID_GEMM 296                     // 2 CTAs x 148 SMs, one wave

__device__ __half g_xa[(size_t)KDIM * KDIM];       // A' fragment-ordered fp16
__device__ __half g_wb[(size_t)KDIM * KDIM];       // B' fragment-ordered fp16
__device__ float  g_part[(size_t)2 * SPLIT_TILES * 128 * 128];  // 17.8 MB
__device__ int    g_flag[SPLIT_TILES];             // pair flags (reset in-kernel)
__device__ int    g_ctr;                           // task counter (reset in prep)

// ---------------------------------------------------------------------------
__device__ __forceinline__ uint32_t smem_u32(const void* p) {
    uint32_t a;
    asm("{ .reg .u64 t; cvta.to.shared.u64 t, %1; cvt.u32.u64 %0, t; }"
        : "=r"(a) : "l"(p));
    return a;
}
__device__ __forceinline__ void cp_async16(uint32_t dst, const void* src) {
    asm volatile("cp.async.cg.shared.global [%0], [%1], 16;"
                 :: "r"(dst), "l"(src) : "memory");
}
__device__ __forceinline__ void cp_commit() {
    asm volatile("cp.async.commit_group;" ::: "memory");
}
__device__ __forceinline__ void cp_wait1() {
    asm volatile("cp.async.wait_group 1;" ::: "memory");
}
__device__ __forceinline__ void lds128(uint32_t* r, uint32_t a) {
    asm volatile("ld.shared.v4.b32 {%0,%1,%2,%3}, [%4];"
                 : "=r"(r[0]), "=r"(r[1]), "=r"(r[2]), "=r"(r[3]) : "r"(a));
}
__device__ __forceinline__ void mma_f16(float* c, const uint32_t* a, const uint32_t* b) {
    asm volatile(
        "mma.sync.aligned.m16n8k16.row.col.f32.f16.f16.f32 "
        "{%0,%1,%2,%3}, {%4,%5,%6,%7}, {%8,%9}, {%0,%1,%2,%3};"
        : "+f"(c[0]), "+f"(c[1]), "+f"(c[2]), "+f"(c[3])
        : "r"(a[0]), "r"(a[1]), "r"(a[2]), "r"(a[3]), "r"(b[0]), "r"(b[1]));
}
__device__ __forceinline__ uint32_t pack_h2(float lo, float hi) {
    __half2 h = __floats2half2_rn(lo, hi);
    return *reinterpret_cast<uint32_t*>(&h);
}

// ---------------------------------------------------------------------------
// Fused pre-pass (unchanged from r14) + task-counter reset.
// Blocks [0,2048): A.  A idx: [m128:5][kb:7][mt16:3][ks:1][lane:5] (16B frag)
// Blocks [2048,4096): B. B idx: [n128:5][kb:7][nt8:4][lane:5] (16B frag =
//   both ks steps: {b0_ks0, b1_ks0, b0_ks1, b1_ks1})
// ---------------------------------------------------------------------------
__device__ __forceinline__ void do_prep_a(const float* __restrict__ xa,
                                          uint4* __restrict__ da, int idx) {
    const int lane = idx & 31;
    const int ks   = (idx >> 5) & 1;
    const int mt16 = (idx >> 6) & 7;
    const int kb   = (idx >> 9) & 127;
    const int m128 = idx >> 16;
    const int row = m128 * 128 + mt16 * 16 + (lane >> 2);
    const int col = kb * 32 + ks * 16 + (lane & 3) * 2;
    const float* p = xa + (size_t)row * KDIM + col;
    const float2 v00 = *reinterpret_cast<const float2*>(p);
    const float2 v10 = *reinterpret_cast<const float2*>(p + (size_t)8 * KDIM);
    const float2 v01 = *reinterpret_cast<const float2*>(p + 8);
    const float2 v11 = *reinterpret_cast<const float2*>(p + (size_t)8 * KDIM + 8);
    uint4 o;
    o.x = pack_h2(v00.x, v00.y);
    o.y = pack_h2(v10.x, v10.y);
    o.z = pack_h2(v01.x, v01.y);
    o.w = pack_h2(v11.x, v11.y);
    da[idx] = o;
}
__device__ __forceinline__ void do_prep_b(const float* __restrict__ wb,
                                          uint4* __restrict__ db, int idx) {
    const int lane = idx & 31;
    const int nt8  = (idx >> 5) & 15;
    const int kb   = (idx >> 9) & 127;
    const int n128 = idx >> 16;
    const int n = n128 * 128 + nt8 * 8 + (lane >> 2);
    const int k = kb * 32 + (lane & 3) * 2;
    const float* p = wb + (size_t)n * KDIM + k;
    const float2 v0 = *reinterpret_cast<const float2*>(p);
    const float2 v1 = *reinterpret_cast<const float2*>(p + 8);
    const float2 v2 = *reinterpret_cast<const float2*>(p + 16);
    const float2 v3 = *reinterpret_cast<const float2*>(p + 24);
    uint4 o;
    o.x = pack_h2(v0.x, v0.y);
    o.y = pack_h2(v1.x, v1.y);
    o.z = pack_h2(v2.x, v2.y);
    o.w = pack_h2(v3.x, v3.y);
    db[idx] = o;
}
__global__ void __launch_bounds__(256) prep_ab(const float* __restrict__ xa,
                                               const float* __restrict__ wb,
                                               uint4* __restrict__ da,
                                               uint4* __restrict__ db) {
    const int bid = blockIdx.x;
    if (bid == 0 && threadIdx.x == 0) g_ctr = 0;   // reset task queue per replay
    if (bid < 2048) {
        const int idx = bid * 256 + threadIdx.x;
        #pragma unroll
        for (int j = 0; j < 4; j++)
            do_prep_a(xa, da, idx + j * (1 << 19));
    } else {
        const int idx = (bid - 2048) * 256 + threadIdx.x;
        #pragma unroll
        for (int j = 0; j < 4; j++)
            do_prep_b(wb, db, idx + j * (1 << 19));
    }
}

// ---------------------------------------------------------------------------
// Persistent GEMM: 296 CTAs x 128 threads (2/SM), dynamic task queue.
// Task tau < 888: full tile. tau >= 888: half-K piece (j = tau-888).
// ---------------------------------------------------------------------------
__global__ void __launch_bounds__(128, 2) gemm_f16_mma(
    const __half* __restrict__ Ap,
    const __half* __restrict__ Bp,
    const float* __restrict__ bias,
    float* __restrict__ out,
    float* __restrict__ part)
{
    extern __shared__ char smem[];
    __shared__ int s_task;
    __shared__ int s_role;
    const uint32_t sb = smem_u32(smem);

    const int tid  = threadIdx.x;
    const int lane = tid & 31;
    const int warp = tid >> 5;
    const int wm   = warp & 1;
    const int wn   = warp >> 1;

    const int fr = lane >> 2;
    const int lrow0 = wm * 64 + fr;
    const int lcol0 = wn * 64 + 2 * (lane & 3);

    const uint32_t aFragBase = sb + (uint32_t)wm * 4096 + lane * 16;
    const uint32_t bFragBase = sb + A_STG + (uint32_t)wn * 4096 + lane * 16;

    for (;;) {
        if (tid == 0) s_task = atomicAdd(&g_ctr, 1);
        __syncthreads();
        const int tau = s_task;
        if (tau >= NTASKS) break;

        int t, k0, kiters;
        if (tau < FULL_TILES) { t = tau; k0 = 0; kiters = 64; }
        else {
            const int j = tau - FULL_TILES;
            t = FULL_TILES + (j >> 1);
            k0 = (j & 1) * 32;
            kiters = 32;
        }
        const int m128 = t & 31;
        const int n128 = t >> 5;

        const char* gA = (const char*)Ap + (size_t)m128 * (128 * KDIM * 2)
                                         + (size_t)k0 * A_STG + tid * 16;
        const char* gB = (const char*)Bp + (size_t)n128 * (128 * KDIM * 2)
                                         + (size_t)k0 * B_STG + tid * 16;

        float acc[4][8][4];
        #pragma unroll
        for (int i = 0; i < 4; i++)
            #pragma unroll
            for (int j2 = 0; j2 < 8; j2++)
                #pragma unroll
                for (int r = 0; r < 4; r++) acc[i][j2][r] = 0.f;

        // ---- prologue: fill stages 0,1 ----
        #pragma unroll
        for (int s = 0; s < STAGES - 1; s++) {
            const uint32_t d = sb + s * STG + tid * 16;
            const char* srcA = gA + (size_t)s * A_STG;
            const char* srcB = gB + (size_t)s * B_STG;
            #pragma unroll
            for (int i = 0; i < 8; i++) {
                cp_async16(d + i * 2048, srcA + i * 2048);
                cp_async16(d + A_STG + i * 2048, srcB + i * 2048);
            }
            cp_commit();
        }

        // ---- mainloop ----
        const char* rA = gA + (size_t)(STAGES - 1) * A_STG;
        const char* rB = gB + (size_t)(STAGES - 1) * B_STG;
        uint32_t st     = 0;
        uint32_t stFill = (STAGES - 1) * STG;

        #pragma unroll 1
        for (int k = 0; k < kiters; k++) {
            cp_wait1();
            __syncthreads();

            const uint32_t ab = aFragBase + st;
            const uint32_t bb = bFragBase + st;

            uint32_t a0[4][4], a1[4][4];
            uint32_t bp[2][4];

            // kh0 A loads
            #pragma unroll
            for (int mt = 0; mt < 4; mt++) {
                lds128(a0[mt], ab + mt * 1024);
                lds128(a1[mt], ab + 512 + mt * 1024);
            }

            // refill stage k+2
            if (k + STAGES - 1 < kiters) {
                const uint32_t d = sb + stFill + tid * 16;
                #pragma unroll
                for (int i = 0; i < 8; i++) {
                    cp_async16(d + i * 2048, rA + i * 2048);
                    cp_async16(d + A_STG + i * 2048, rB + i * 2048);
                }
            }
            cp_commit();

            // kh0: rolling B, MMAs
            lds128(bp[0], bb);
            #pragma unroll
            for (int nt = 0; nt < 8; nt++) {
                const int cur = nt & 1;
                if (nt < 7) lds128(bp[cur ^ 1], bb + (nt + 1) * 512);
                else        lds128(bp[cur ^ 1], bb + 8192);
                #pragma unroll
                for (int mt = 0; mt < 4; mt++)
                    mma_f16(acc[mt][nt], a0[mt], &bp[cur][0]);
                #pragma unroll
                for (int mt = 0; mt < 4; mt++)
                    mma_f16(acc[mt][nt], a1[mt], &bp[cur][2]);
            }

            // kh1 A loads
            #pragma unroll
            for (int mt = 0; mt < 4; mt++) {
                lds128(a0[mt], ab + 8192 + mt * 1024);
                lds128(a1[mt], ab + 8192 + 512 + mt * 1024);
            }

            // kh1: bp[0] already holds nt0
            #pragma unroll
            for (int nt = 0; nt < 8; nt++) {
                const int cur = nt & 1;
                if (nt < 7) lds128(bp[cur ^ 1], bb + 8192 + (nt + 1) * 512);
                #pragma unroll
                for (int mt = 0; mt < 4; mt++)
                    mma_f16(acc[mt][nt], a0[mt], &bp[cur][0]);
                #pragma unroll
                for (int mt = 0; mt < 4; mt++)
                    mma_f16(acc[mt][nt], a1[mt], &bp[cur][2]);
            }

            st += STG;     if (st     == STAGES * STG) st = 0;
            stFill += STG; if (stFill == STAGES * STG) stFill = 0;
            rA += A_STG;
            rB += B_STG;
        }

        // ---- epilogue ----
        if (tau < FULL_TILES) {
            const int orow0 = m128 * 128 + lrow0;
            const int ocol0 = n128 * 128 + lcol0;
            float2 bv[8];
            #pragma unroll
            for (int nt = 0; nt < 8; nt++)
                bv[nt] = *reinterpret_cast<const float2*>(bias + ocol0 + nt * 8);
            #pragma unroll
            for (int mt = 0; mt < 4; mt++) {
                const int r0 = orow0 + mt * 16;
                #pragma unroll
                for (int nt = 0; nt < 8; nt++) {
                    const int col = ocol0 + nt * 8;
                    float2 v0 = { acc[mt][nt][0] + bv[nt].x, acc[mt][nt][1] + bv[nt].y };
                    float2 v1 = { acc[mt][nt][2] + bv[nt].x, acc[mt][nt][3] + bv[nt].y };
                    *reinterpret_cast<float2*>(out + (size_t)r0 * KDIM + col) = v0;
                    *reinterpret_cast<float2*>(out + (size_t)(r0 + 8) * KDIM + col) = v1;
                }
            }
        } else {
            // Symmetric split-K: write my slot; second finisher reduces.
            const int j    = tau - FULL_TILES;
            const int pair = j >> 1;
            float* mySlot  = part + (size_t)j * (128 * 128);
            float* othSlot = part + (size_t)(j ^ 1) * (128 * 128);

            #pragma unroll
            for (int mt = 0; mt < 4; mt++) {
                const int r0 = lrow0 + mt * 16;
                #pragma unroll
                for (int nt = 0; nt < 8; nt++) {
                    const int col = lcol0 + nt * 8;
                    float2 v0 = { acc[mt][nt][0], acc[mt][nt][1] };
                    float2 v1 = { acc[mt][nt][2], acc[mt][nt][3] };
                    *reinterpret_cast<float2*>(mySlot + r0 * 128 + col) = v0;
                    *reinterpret_cast<float2*>(mySlot + (r0 + 8) * 128 + col) = v1;
                }
            }
            __threadfence();
            __syncthreads();
            if (tid == 0) {
                const int old = atomicExch(&g_flag[pair], 1);
                s_role = old;                 // 0 = first (done), 1 = second (reduce)
                if (old == 1) g_flag[pair] = 0;   // reset for next replay
            }
            __syncthreads();

            if (s_role == 1) {
                __threadfence();   // acquire partner's slot
                const int orow0 = m128 * 128 + lrow0;
                const int ocol0 = n128 * 128 + lcol0;
                float2 bv[8];
                #pragma unroll
                for (int nt = 0; nt < 8; nt++)
                    bv[nt] = *reinterpret_cast<const float2*>(bias + ocol0 + nt * 8);
                #pragma unroll
                for (int mt = 0; mt < 4; mt++) {
                    const int r0l = lrow0 + mt * 16;
                    const int r0g = orow0 + mt * 16;
                    #pragma unroll
                    for (int nt = 0; nt < 8; nt++) {
                        const int col = lcol0 + nt * 8;
                        const float2 p0 = *reinterpret_cast<const float2*>(othSlot + r0l * 128 + col);
                        const float2 p1 = *reinterpret_cast<const float2*>(othSlot + (r0l + 8) * 128 + col);
                        const int gcol = ocol0 + nt * 8;
                        float2 v0 = { acc[mt][nt][0] + p0.x + bv[nt].x,
                                      acc[mt][nt][1] + p0.y + bv[nt].y };
                        float2 v1 = { acc[mt][nt][2] + p1.x + bv[nt].x,
                                      acc[mt][nt][3] + p1.y + bv[nt].y };
                        *reinterpret_cast<float2*>(out + (size_t)r0g * KDIM + gcol) = v0;
                        *reinterpret_cast<float2*>(out + (size_t)(r0g + 8) * KDIM + gcol) = v1;
                    }
                }
            }
        }
        __syncthreads();   // all threads done with s_task/s_role before next pop
    }
}

// ---------------------------------------------------------------------------
extern "C" void kernel_launch(void* const* d_in, const int* in_sizes, int n_in,
                              void* d_out, int out_size) {
    const float* x    = (const float*)d_in[0];
    const float* w    = (const float*)d_in[1];
    const float* bias = (const float*)d_in[2];
    float* out        = (float*)d_out;

    void* gx = nullptr;
    void* gw = nullptr;
    void* gp = nullptr;
    cudaGetSymbolAddress(&gx, g_xa);
    cudaGetSymbolAddress(&gw, g_wb);
    cudaGetSymbolAddress(&gp, g_part);

    static bool attr_set = false;  // host-side only
    if (!attr_set) {
        cudaFuncSetAttribute(gemm_f16_mma,
                             cudaFuncAttributeMaxDynamicSharedMemorySize, SMEM_TOTAL);
        attr_set = true;
    }

    prep_ab<<<4096, 256>>>(x, w, (uint4*)gx, (uint4*)gw);

    gemm_f16_mma<<<GRID_GEMM, 128, SMEM_TOTAL>>>(
        (const __half*)gx, (const __half*)gw, bias, out, (float*)gp);
}

// round 16
// speedup vs baseline: 1.3005x; 1.3005x over previous
#include <cuda_runtime.h>
#include <cuda_fp16.h>
#include <cstdint>

// ============================================================================
// y = x @ W^T + b (4096^3 fp32), mma.sync.m16n8k16.f32.f16.f16.f32.
//
// Round-16 = round-14 (best: 307.4us) reverted from the failed persistent
// experiment, plus streaming (__ldcs, evict-first) source reads in prep so
// x/W don't evict the fragment arrays from L2 (GEMM wave-1 reads them).
//
// Structure: CTA tile 128x128, 4 warps of 64x64, BK=64, 3-stage cp.async,
// 2 CTA/SM, SW-pipelined (kh,ks) steps, B fragments packing both ks-steps
// per 16B (lds128-only mainloop), hybrid split-K tail (888 full-K CTAs =
// 3 full waves + 272 half-K CTAs in a half-length 4th wave) with the
// reduction fused into the GEMM via paired-CTA flag handoff.
// ============================================================================

#define KDIM 4096
#define STAGES 3
#define A_STG 16384                       // 128 x 64 x 2B
#define B_STG 16384
#define STG (A_STG + B_STG)               // 32768
#define SMEM_TOTAL (STAGES * STG)         // 98304

#define FULL_TILES 888                    // 3 x 296
#define SPLIT_TILES 136                   // 1024 - 888
#define GRID_GEMM (FULL_TILES + 2 * SPLIT_TILES)   // 1160

__device__ __half g_xa[(size_t)KDIM * KDIM];       // A' fragment-ordered fp16
__device__ __half g_wb[(size_t)KDIM * KDIM];       // B' fragment-ordered fp16
__device__ float  g_part[(size_t)SPLIT_TILES * 128 * 128];  // 8.9 MB partials
__device__ int    g_flag[SPLIT_TILES];             // zero-init; reset by reducer

// ---------------------------------------------------------------------------
__device__ __forceinline__ uint32_t smem_u32(const void* p) {
    uint32_t a;
    asm("{ .reg .u64 t; cvta.to.shared.u64 t, %1; cvt.u32.u64 %0, t; }"
        : "=r"(a) : "l"(p));
    return a;
}
__device__ __forceinline__ void cp_async16(uint32_t dst, const void* src) {
    asm volatile("cp.async.cg.shared.global [%0], [%1], 16;"
                 :: "r"(dst), "l"(src) : "memory");
}
__device__ __forceinline__ void cp_commit() {
    asm volatile("cp.async.commit_group;" ::: "memory");
}
__device__ __forceinline__ void cp_wait1() {
    asm volatile("cp.async.wait_group 1;" ::: "memory");
}
__device__ __forceinline__ void lds128(uint32_t* r, uint32_t a) {
    asm volatile("ld.shared.v4.b32 {%0,%1,%2,%3}, [%4];"
                 : "=r"(r[0]), "=r"(r[1]), "=r"(r[2]), "=r"(r[3]) : "r"(a));
}
__device__ __forceinline__ void mma_f16(float* c, const uint32_t* a, const uint32_t* b) {
    asm volatile(
        "mma.sync.aligned.m16n8k16.row.col.f32.f16.f16.f32 "
        "{%0,%1,%2,%3}, {%4,%5,%6,%7}, {%8,%9}, {%0,%1,%2,%3};"
        : "+f"(c[0]), "+f"(c[1]), "+f"(c[2]), "+f"(c[3])
        : "r"(a[0]), "r"(a[1]), "r"(a[2]), "r"(a[3]), "r"(b[0]), "r"(b[1]));
}
__device__ __forceinline__ uint32_t pack_h2(float lo, float hi) {
    __half2 h = __floats2half2_rn(lo, hi);
    return *reinterpret_cast<uint32_t*>(&h);
}
// streaming (evict-first) float2 load
__device__ __forceinline__ float2 ldcs_f2(const float* p) {
    float2 v;
    asm volatile("ld.global.cs.v2.f32 {%0,%1}, [%2];"
                 : "=f"(v.x), "=f"(v.y) : "l"(p));
    return v;
}

// ---------------------------------------------------------------------------
// Fused pre-pass: fp32 -> fp16 (RN) into mma fragment order. 4 frags/thread.
// Blocks [0,2048): A.  A idx: [m128:5][kb:7][mt16:3][ks:1][lane:5] (16B frag)
// Blocks [2048,4096): B. B idx: [n128:5][kb:7][nt8:4][lane:5] (16B frag =
//   both ks steps: {b0_ks0, b1_ks0, b0_ks1, b1_ks1})
// Source reads are .cs (streaming) so x/W don't evict fragments from L2.
// ---------------------------------------------------------------------------
__device__ __forceinline__ void do_prep_a(const float* __restrict__ xa,
                                          uint4* __restrict__ da, int idx) {
    const int lane = idx & 31;
    const int ks   = (idx >> 5) & 1;
    const int mt16 = (idx >> 6) & 7;
    const int kb   = (idx >> 9) & 127;
    const int m128 = idx >> 16;
    const int row = m128 * 128 + mt16 * 16 + (lane >> 2);
    const int col = kb * 32 + ks * 16 + (lane & 3) * 2;
    const float* p = xa + (size_t)row * KDIM + col;
    const float2 v00 = ldcs_f2(p);
    const float2 v10 = ldcs_f2(p + (size_t)8 * KDIM);
    const float2 v01 = ldcs_f2(p + 8);
    const float2 v11 = ldcs_f2(p + (size_t)8 * KDIM + 8);
    uint4 o;
    o.x = pack_h2(v00.x, v00.y);
    o.y = pack_h2(v10.x, v10.y);
    o.z = pack_h2(v01.x, v01.y);
    o.w = pack_h2(v11.x, v11.y);
    da[idx] = o;
}
__device__ __forceinline__ void do_prep_b(const float* __restrict__ wb,
                                          uint4* __restrict__ db, int idx) {
    const int lane = idx & 31;
    const int nt8  = (idx >> 5) & 15;
    const int kb   = (idx >> 9) & 127;
    const int n128 = idx >> 16;
    const int n = n128 * 128 + nt8 * 8 + (lane >> 2);
    const int k = kb * 32 + (lane & 3) * 2;
    const float* p = wb + (size_t)n * KDIM + k;
    const float2 v0 = ldcs_f2(p);        // ks0 b0
    const float2 v1 = ldcs_f2(p + 8);    // ks0 b1
    const float2 v2 = ldcs_f2(p + 16);   // ks1 b0
    const float2 v3 = ldcs_f2(p + 24);   // ks1 b1
    uint4 o;
    o.x = pack_h2(v0.x, v0.y);
    o.y = pack_h2(v1.x, v1.y);
    o.z = pack_h2(v2.x, v2.y);
    o.w = pack_h2(v3.x, v3.y);
    db[idx] = o;
}
__global__ void __launch_bounds__(256) prep_ab(const float* __restrict__ xa,
                                               const float* __restrict__ wb,
                                               uint4* __restrict__ da,
                                               uint4* __restrict__ db) {
    const int bid = blockIdx.x;
    if (bid < 2048) {
        const int idx = bid * 256 + threadIdx.x;            // [0, 2^19)
        #pragma unroll
        for (int j = 0; j < 4; j++)
            do_prep_a(xa, da, idx + j * (1 << 19));
    } else {
        const int idx = (bid - 2048) * 256 + threadIdx.x;   // [0, 2^19)
        #pragma unroll
        for (int j = 0; j < 4; j++)
            do_prep_b(wb, db, idx + j * (1 << 19));
    }
}

// ---------------------------------------------------------------------------
// GEMM: 128 threads, 4 warps (2 wm x 2 wn of 64x64 warp tiles), 2 CTA/SM.
// bid < 888: full tile. bid >= 888: split-K half; odd half writes partial,
// even half fuses the reduction.
// ---------------------------------------------------------------------------
__global__ void __launch_bounds__(128, 2) gemm_f16_mma(
    const __half* __restrict__ Ap,
    const __half* __restrict__ Bp,
    const float* __restrict__ bias,
    float* __restrict__ out,
    float* __restrict__ part)
{
    extern __shared__ char smem[];
    const uint32_t sb = smem_u32(smem);

    const int tid  = threadIdx.x;
    const int lane = tid & 31;
    const int warp = tid >> 5;
    const int wm   = warp & 1;     // 2 warp rows (64 each)
    const int wn   = warp >> 1;    // 2 warp cols (64 each)

    const int bid = blockIdx.x;
    int t, k0, kiters;
    if (bid < FULL_TILES) { t = bid; k0 = 0; kiters = 64; }
    else {
        const int j = bid - FULL_TILES;
        t = FULL_TILES + (j >> 1);
        k0 = (j & 1) * 32;
        kiters = 32;
    }
    const int m128 = t & 31;            // M fastest (B-tile L2 reuse)
    const int n128 = t >> 5;

    const char* gA = (const char*)Ap + (size_t)m128 * (128 * KDIM * 2)
                                     + (size_t)k0 * A_STG + tid * 16;
    const char* gB = (const char*)Bp + (size_t)n128 * (128 * KDIM * 2)
                                     + (size_t)k0 * B_STG + tid * 16;

    const uint32_t aFragBase = sb + (uint32_t)wm * 4096 + lane * 16;
    const uint32_t bFragBase = sb + A_STG + (uint32_t)wn * 4096 + lane * 16;

    float acc[4][8][4];
    #pragma unroll
    for (int i = 0; i < 4; i++)
        #pragma unroll
        for (int j = 0; j < 8; j++)
            #pragma unroll
            for (int r = 0; r < 4; r++) acc[i][j][r] = 0.f;

    // ---- prologue: fill stages 0,1 ----
    #pragma unroll
    for (int s = 0; s < STAGES - 1; s++) {
        const uint32_t d = sb + s * STG + tid * 16;
        const char* srcA = gA + (size_t)s * A_STG;
        const char* srcB = gB + (size_t)s * B_STG;
        #pragma unroll
        for (int i = 0; i < 8; i++) {
            cp_async16(d + i * 2048, srcA + i * 2048);
            cp_async16(d + A_STG + i * 2048, srcB + i * 2048);
        }
        cp_commit();
    }

    // ---- mainloop ----
    const char* rA = gA + (size_t)(STAGES - 1) * A_STG;
    const char* rB = gB + (size_t)(STAGES - 1) * B_STG;
    uint32_t st     = 0;
    uint32_t stFill = (STAGES - 1) * STG;

    #pragma unroll 1
    for (int k = 0; k < kiters; k++) {
        cp_wait1();
        __syncthreads();

        const uint32_t ab = aFragBase + st;
        const uint32_t bb = bFragBase + st;

        uint32_t a0[4][4], a1[4][4];   // A frags ks0/ks1 of current kh
        uint32_t bp[2][4];             // rolling B pair (both ks in one frag)

        // kh0 A loads
        #pragma unroll
        for (int mt = 0; mt < 4; mt++) {
            lds128(a0[mt], ab + mt * 1024);
            lds128(a1[mt], ab + 512 + mt * 1024);
        }

        // refill stage k+2
        if (k + STAGES - 1 < kiters) {
            const uint32_t d = sb + stFill + tid * 16;
            #pragma unroll
            for (int i = 0; i < 8; i++) {
                cp_async16(d + i * 2048, rA + i * 2048);
                cp_async16(d + A_STG + i * 2048, rB + i * 2048);
            }
        }
        cp_commit();

        // kh0: rolling B, MMAs
        lds128(bp[0], bb);
        #pragma unroll
        for (int nt = 0; nt < 8; nt++) {
            const int cur = nt & 1;
            if (nt < 7) lds128(bp[cur ^ 1], bb + (nt + 1) * 512);
            else        lds128(bp[cur ^ 1], bb + 8192);          // kh1 nt0
            #pragma unroll
            for (int mt = 0; mt < 4; mt++)
                mma_f16(acc[mt][nt], a0[mt], &bp[cur][0]);
            #pragma unroll
            for (int mt = 0; mt < 4; mt++)
                mma_f16(acc[mt][nt], a1[mt], &bp[cur][2]);
        }

        // kh1 A loads
        #pragma unroll
        for (int mt = 0; mt < 4; mt++) {
            lds128(a0[mt], ab + 8192 + mt * 1024);
            lds128(a1[mt], ab + 8192 + 512 + mt * 1024);
        }

        // kh1: bp[0] already holds nt0
        #pragma unroll
        for (int nt = 0; nt < 8; nt++) {
            const int cur = nt & 1;
            if (nt < 7) lds128(bp[cur ^ 1], bb + 8192 + (nt + 1) * 512);
            #pragma unroll
            for (int mt = 0; mt < 4; mt++)
                mma_f16(acc[mt][nt], a0[mt], &bp[cur][0]);
            #pragma unroll
            for (int mt = 0; mt < 4; mt++)
                mma_f16(acc[mt][nt], a1[mt], &bp[cur][2]);
        }

        st += STG;     if (st     == STAGES * STG) st = 0;
        stFill += STG; if (stFill == STAGES * STG) stFill = 0;
        rA += A_STG;
        rB += B_STG;
    }

    // ---- epilogue ----
    const int fr = lane >> 2;
    const int lrow0 = wm * 64 + fr;
    const int lcol0 = wn * 64 + 2 * (lane & 3);

    if (bid < FULL_TILES) {
        const int orow0 = m128 * 128 + lrow0;
        const int ocol0 = n128 * 128 + lcol0;
        float2 bv[8];
        #pragma unroll
        for (int nt = 0; nt < 8; nt++)
            bv[nt] = *reinterpret_cast<const float2*>(bias + ocol0 + nt * 8);
        #pragma unroll
        for (int mt = 0; mt < 4; mt++) {
            const int r0 = orow0 + mt * 16;
            #pragma unroll
            for (int nt = 0; nt < 8; nt++) {
                const int col = ocol0 + nt * 8;
                float2 v0 = { acc[mt][nt][0] + bv[nt].x, acc[mt][nt][1] + bv[nt].y };
                float2 v1 = { acc[mt][nt][2] + bv[nt].x, acc[mt][nt][3] + bv[nt].y };
                *reinterpret_cast<float2*>(out + (size_t)r0 * KDIM + col) = v0;
                *reinterpret_cast<float2*>(out + (size_t)(r0 + 8) * KDIM + col) = v1;
            }
        }
    } else {
        const int j    = bid - FULL_TILES;
        const int pair = j >> 1;
        volatile int* flag = (volatile int*)&g_flag[pair];
        float* pt = part + (size_t)pair * (128 * 128);

        if (j & 1) {
            // writer half: store raw partial, release flag
            #pragma unroll
            for (int mt = 0; mt < 4; mt++) {
                const int r0 = lrow0 + mt * 16;
                #pragma unroll
                for (int nt = 0; nt < 8; nt++) {
                    const int col = lcol0 + nt * 8;
                    float2 v0 = { acc[mt][nt][0], acc[mt][nt][1] };
                    float2 v1 = { acc[mt][nt][2], acc[mt][nt][3] };
                    *reinterpret_cast<float2*>(pt + r0 * 128 + col) = v0;
                    *reinterpret_cast<float2*>(pt + (r0 + 8) * 128 + col) = v1;
                }
            }
            __threadfence();
            __syncthreads();
            if (tid == 0) *flag = 1;
        } else {
            // reducer half: poll, add partner + bias, write out, reset flag
            if (tid == 0) {
                while (*flag == 0) { __nanosleep(64); }
                *flag = 0;   // reset for next graph replay
            }
            __syncthreads();
            __threadfence();   // acquire: partner's partial now visible

            const int orow0 = m128 * 128 + lrow0;
            const int ocol0 = n128 * 128 + lcol0;
            float2 bv[8];
            #pragma unroll
            for (int nt = 0; nt < 8; nt++)
                bv[nt] = *reinterpret_cast<const float2*>(bias + ocol0 + nt * 8);
            #pragma unroll
            for (int mt = 0; mt < 4; mt++) {
                const int r0l = lrow0 + mt * 16;
                const int r0g = orow0 + mt * 16;
                #pragma unroll
                for (int nt = 0; nt < 8; nt++) {
                    const int col = lcol0 + nt * 8;
                    const float2 p0 = *reinterpret_cast<const float2*>(pt + r0l * 128 + col);
                    const float2 p1 = *reinterpret_cast<const float2*>(pt + (r0l + 8) * 128 + col);
                    const int gcol = ocol0 + nt * 8;
                    float2 v0 = { acc[mt][nt][0] + p0.x + bv[nt].x,
                                  acc[mt][nt][1] + p0.y + bv[nt].y };
                    float2 v1 = { acc[mt][nt][2] + p1.x + bv[nt].x,
                                  acc[mt][nt][3] + p1.y + bv[nt].y };
                    *reinterpret_cast<float2*>(out + (size_t)r0g * KDIM + gcol) = v0;
                    *reinterpret_cast<float2*>(out + (size_t)(r0g + 8) * KDIM + gcol) = v1;
                }
            }
        }
    }
}

// ---------------------------------------------------------------------------
extern "C" void kernel_launch(void* const* d_in, const int* in_sizes, int n_in,
                              void* d_out, int out_size) {
    const float* x    = (const float*)d_in[0];
    const float* w    = (const float*)d_in[1];
    const float* bias = (const float*)d_in[2];
    float* out        = (float*)d_out;

    void* gx = nullptr;
    void* gw = nullptr;
    void* gp = nullptr;
    cudaGetSymbolAddress(&gx, g_xa);
    cudaGetSymbolAddress(&gw, g_wb);
    cudaGetSymbolAddress(&gp, g_part);

    static bool attr_set = false;  // host-side only
    if (!attr_set) {
        cudaFuncSetAttribute(gemm_f16_mma,
                             cudaFuncAttributeMaxDynamicSharedMemorySize, SMEM_TOTAL);
        attr_set = true;
    }

    prep_ab<<<4096, 256>>>(x, w, (uint4*)gx, (uint4*)gw);

    gemm_f16_mma<<<GRID_GEMM, 128, SMEM_TOTAL>>>(
        (const __half*)gx, (const __half*)gw, bias, out, (float*)gp);
}